// round 12
// baseline (speedup 1.0000x reference)
#include <cuda_runtime.h>
#include <cstdint>

#define NB 2048
#define NWORDS (NB / 64)                     // 32
#define NTILES (NWORDS * (NWORDS + 1) / 2)   // 528 upper-tri blocks
#define CAP_ROWS 192                         // suppressor-row smem cache capacity
#define SCAN_DYN_BYTES (CAP_ROWS * NWORDS * 8)   // 48KB

typedef unsigned long long u64;
typedef unsigned int u32;
typedef unsigned short u16;

// ---------------- device scratch ----------------
__device__ int   g_order[NB];              // sorted pos -> original index
__device__ __align__(16) float g_pboxs[NB * 16];  // SORTED: x0..3,y0..3,cx,cy,c,s,we,he,area,rad
__device__ u64   g_mask[NB * NWORDS];      // suppression bitmask; lower-tri never written, stays 0
__device__ u64   g_diag[NB];               // each row's diagonal-block word (contiguous copy)
__device__ u64   g_rownz[NWORDS];          // bit j of word c -> row c*64+j has any suppression
__device__ int   g_done;

// exact (non-contracted) fp32 helpers — replicate jax/XLA unfused fp32 ops
__device__ __forceinline__ float xmul(float a, float b) { return __fmul_rn(a, b); }
__device__ __forceinline__ float xadd(float a, float b) { return __fadd_rn(a, b); }
__device__ __forceinline__ float xsub(float a, float b) { return __fsub_rn(a, b); }
__device__ __forceinline__ float xdiv(float a, float b) { return __fdiv_rn(a, b); }
__device__ __forceinline__ float xcross(float ax, float ay, float bx, float by) {
    return xsub(xmul(ax, by), xmul(ay, bx));
}

// ---------------- kernel 1: fused reduce + keys + rank + trig + precompute ----------------
// 256 blocks x 256 threads; 8 boxes per block (R9 mapping — best measured).
// Rank: warp-per-box, conflict-free interleaved smem scan.
// Trig: threads 0-15, ONE transcendental each (even=cos, odd=sin) -> half-length fp64 tail.
__global__ void __launch_bounds__(256) prep_kernel(const float* __restrict__ boxes,
                                                   const float* __restrict__ scores,
                                                   const int*   __restrict__ labels) {
    __shared__ u32  skeys[NB];
    __shared__ float red[256];
    __shared__ int  sranks[8];
    __shared__ float scos[8], ssin[8];
    const int tid  = threadIdx.x;
    const int warp = tid >> 5;
    const int lane = tid & 31;

    // redundant per-block reductions (max order-invariant; sqrt monotone -> exact)
    float m1 = -1e30f, m2 = -1e30f;
    for (int q = tid; q < NB; q += 256) {
        float cx = boxes[q * 5 + 0], cy = boxes[q * 5 + 1];
        float w  = boxes[q * 5 + 2], h  = boxes[q * 5 + 3];
        float s2 = xadd(xmul(w, w), xmul(h, h));
        m1 = fmaxf(m1, s2);
        m2 = fmaxf(m2, fmaxf(cx, cy));
        skeys[q] = __float_as_uint(scores[q]) ^ 0xFFFFFFFFu;   // ascending == descending score
    }
    red[tid] = m1; __syncthreads();
    for (int s = 128; s > 0; s >>= 1) { if (tid < s) red[tid] = fmaxf(red[tid], red[tid + s]); __syncthreads(); }
    float maxs = __fsqrt_rn(red[0]); __syncthreads();
    red[tid] = m2; __syncthreads();
    for (int s = 128; s > 0; s >>= 1) { if (tid < s) red[tid] = fmaxf(red[tid], red[tid + s]); __syncthreads(); }
    float maxc = red[0];

    // scale = (max_coord + max_radius)*2 + 1  (exact ref fp32 sequence)
    const float scale = xadd(xmul(xadd(maxc, xmul(maxs, 0.5f)), 2.0f), 1.0f);

    if (blockIdx.x == 0) {
        if (tid < NWORDS) g_rownz[tid] = 0ULL;
        if (tid == 0) g_done = 0;
    }

    // ---- trig: threads 0-15, one transcendental each (parallel half-length fp64 chains)
    if (tid < 16) {
        const int bi = tid >> 1;                       // local box 0..7
        const int i  = blockIdx.x * 8 + bi;
        double a = (double)boxes[i * 5 + 4];
        if (tid & 1) ssin[bi] = (float)sin(a);
        else         scos[bi] = (float)cos(a);
    }

    // ---- rank: warp `warp` ranks box i (interleaved -> bank == lane, conflict-free)
    {
        const int i = blockIdx.x * 8 + warp;
        const u32 mykey = skeys[i];
        int rank = 0;
#pragma unroll 16
        for (int q = lane; q < NB; q += 32) {
            u32 kq = skeys[q];
            rank += (kq < mykey) || (kq == mykey && q < i);   // stable tiebreak
        }
#pragma unroll
        for (int off = 16; off > 0; off >>= 1) rank += __shfl_xor_sync(0xFFFFFFFFu, rank, off);
        if (lane == 0) sranks[warp] = rank;
    }
    __syncthreads();

    // ---- precompute: threads 0-7, one box each (fp32 only — no long chains)
    if (tid < 8) {
        const int i = blockIdx.x * 8 + tid;
        const int rank = sranks[tid];

        float off = xmul((float)labels[i], scale);
        float cx = xadd(boxes[i * 5 + 0], off);
        float cy = xadd(boxes[i * 5 + 1], off);
        float w  = boxes[i * 5 + 2];
        float h  = boxes[i * 5 + 3];
        float c  = scos[tid];
        float s  = ssin[tid];
        float wh = xmul(w, 0.5f);
        float hh = xmul(h, 0.5f);

        float P[16];
#pragma unroll
        for (int q = 0; q < 4; q++) {
            float dx = (q == 1 || q == 2) ? wh : -wh;
            float dy = (q >= 2) ? hh : -hh;
            P[q]     = xsub(xadd(cx, xmul(c, dx)), xmul(s, dy));
            P[4 + q] = xadd(xadd(cy, xmul(s, dx)), xmul(c, dy));
        }
        P[8]  = cx;  P[9]  = cy;  P[10] = c;  P[11] = s;
        P[12] = xadd(wh, 1e-5f);
        P[13] = xadd(hh, 1e-5f);
        P[14] = xmul(w, h);
        P[15] = 0.5f * __fsqrt_rn(w * w + h * h) + 1e-2f;   // conservative circle radius

        float4* D = (float4*)&g_pboxs[rank * 16];
        const float4* Ps = (const float4*)P;
#pragma unroll
        for (int q = 0; q < 4; q++) D[q] = Ps[q];
        g_order[rank] = i;
    }
}

// ---------------- exact-replica pairwise intersection area (compacted) ----------------
__device__ __forceinline__ bool pib(float x, float y, const float* __restrict__ B) {
    float px = xsub(x, B[8]);
    float py = xsub(y, B[9]);
    float lx = xadd(xmul(B[10], px), xmul(B[11], py));     //  c*px + s*py
    float ly = xadd(xmul(-B[11], px), xmul(B[10], py));    // -s*px + c*py
    return (fabsf(lx) <= B[12]) && (fabsf(ly) <= B[13]);
}

__device__ float pair_inter_area(const float* __restrict__ A, const float* __restrict__ B) {
    float px[24], py[24];
    int k = 0;
    float sxm = 0.0f, sym = 0.0f;

    // candidate points appended in reference index order 0..23 -> identical fp sum order
#pragma unroll
    for (int q = 0; q < 4; q++) {
        if (pib(A[q], A[4 + q], B)) {
            px[k] = A[q]; py[k] = A[4 + q];
            sxm = xadd(sxm, A[q]); sym = xadd(sym, A[4 + q]); k++;
        }
    }
#pragma unroll
    for (int q = 0; q < 4; q++) {
        if (pib(B[q], B[4 + q], A)) {
            px[k] = B[q]; py[k] = B[4 + q];
            sxm = xadd(sxm, B[q]); sym = xadd(sym, B[4 + q]); k++;
        }
    }
#pragma unroll
    for (int ea = 0; ea < 4; ea++) {
        float pxx = A[ea], pyy = A[4 + ea];
        float rx = xsub(A[(ea + 1) & 3], pxx), ry = xsub(A[4 + ((ea + 1) & 3)], pyy);
#pragma unroll
        for (int eb = 0; eb < 4; eb++) {
            float qx = B[eb], qy = B[4 + eb];
            float sx = xsub(B[(eb + 1) & 3], qx), sy = xsub(B[4 + ((eb + 1) & 3)], qy);
            float den = xcross(rx, ry, sx, sy);
            float qpx = xsub(qx, pxx), qpy = xsub(qy, pyy);
            if (fabsf(den) > 1e-9f) {
                float tt = xdiv(xcross(qpx, qpy, sx, sy), den);
                float uu = xdiv(xcross(qpx, qpy, rx, ry), den);
                if (tt >= 0.0f && tt <= 1.0f && uu >= 0.0f && uu <= 1.0f) {
                    float ix = xadd(pxx, xmul(tt, rx));
                    float iy = xadd(pyy, xmul(tt, ry));
                    px[k] = ix; py[k] = iy;
                    sxm = xadd(sxm, ix); sym = xadd(sym, iy); k++;
                }
            }
        }
    }
    if (k < 3) return 0.0f;

    float kk  = (float)k;
    float cxm = xdiv(sxm, kk), cym = xdiv(sym, kk);

    float dxr[24], dyr[24];
    u64 key[24];
    for (int q = 0; q < k; q++) {
        float dx = xsub(px[q], cxm);
        float dy = xsub(py[q], cym);
        dxr[q] = dx; dyr[q] = dy;
        float a = atan2f(dy, dx);
        u32 b = __float_as_uint(a);
        b = (b & 0x80000000u) ? ~b : (b | 0x80000000u);   // monotone map
        key[q] = ((u64)b << 5) | (u32)q;                   // unique -> stable order
    }
    for (int q = 1; q < k; q++) {          // insertion sort, k typically 4-8
        u64 kq = key[q]; int r = q - 1;
        while (r >= 0 && key[r] > kq) { key[r + 1] = key[r]; r--; }
        key[r + 1] = kq;
    }

    float tot = 0.0f;
    for (int q = 0; q < k; q++) {
        int nq = (q + 1 < k) ? q + 1 : 0;
        int a0 = (int)(key[q]  & 31u);
        int a1 = (int)(key[nq] & 31u);
        tot = xadd(tot, xcross(dxr[a0], dyr[a0], dxr[a1], dyr[a1]));
    }
    return xmul(0.5f, fabsf(tot));
}

// ---------------- kernel 2: fused filter + IoU + (last block) greedy scan ----------------
__device__ __forceinline__ u64 morton_even(u32 x) {
    u64 v = x;
    v = (v | (v << 16)) & 0x0000FFFF0000FFFFULL;
    v = (v | (v << 8))  & 0x00FF00FF00FF00FFULL;
    v = (v | (v << 4))  & 0x0F0F0F0F0F0F0F0FULL;
    v = (v | (v << 2))  & 0x3333333333333333ULL;
    v = (v | (v << 1))  & 0x5555555555555555ULL;
    return v;
}

__global__ void __launch_bounds__(256) mask_scan_kernel(const float* __restrict__ thrp,
                                                        const float* __restrict__ scores,
                                                        float* __restrict__ out) {
    extern __shared__ u64 rowsbuf[];     // CAP_ROWS x NWORDS words (dynamic, 48KB; scan tail only)
    __shared__ __align__(16) union {
        struct { float sA[1024]; float sB[1024]; u16 queue[4096]; } m;   // 16.5KB (mask phase)
        u64 sdiag[NB];                                                   // 16KB  (scan tail)
    } shm;
    __shared__ u64 sbits[64];
    __shared__ int qcnt, is_last;
    __shared__ u64 snz[NWORDS], s_keep[NWORDS];
    __shared__ int cbase[NWORDS + 1];
    __shared__ int rowid[CAP_ROWS];

    // linear blockIdx -> upper-tri (by, bx)
    int b = blockIdx.x;
    int by = 0;
    while (b >= NWORDS - by) { b -= NWORDS - by; by++; }
    const int bx = by + b;
    const int t = threadIdx.x;

    {   // float4 tile loads
        const float4* srcB = (const float4*)&g_pboxs[bx * 1024];
        const float4* srcA = (const float4*)&g_pboxs[by * 1024];
        float4* dB = (float4*)shm.m.sB;
        float4* dA = (float4*)shm.m.sA;
        if (t < 256) { dB[t] = srcB[t]; dA[t] = srcA[t]; }
    }
    if (t < 64) sbits[t] = 0ULL;
    if (t == 0) qcnt = 0;
    __syncthreads();

    // circle filter: 4 threads per row, 16 columns each
    {
        const int row = t & 63;
        const int qtr = t >> 6;
        const float acx = shm.m.sA[row * 16 + 8];
        const float acy = shm.m.sA[row * 16 + 9];
        const float ard = shm.m.sA[row * 16 + 15];
        const int jlo = (bx == by) ? row + 1 : 0;
        const int j0 = qtr * 16, j1 = j0 + 16;
        for (int j = j0; j < j1; j++) {
            if (j < jlo) continue;
            float dx = acx - shm.m.sB[j * 16 + 8], dy = acy - shm.m.sB[j * 16 + 9];
            float rr = ard + shm.m.sB[j * 16 + 15];
            if (dx * dx + dy * dy <= rr * rr) {          // circle overlap -> candidate
                int q = atomicAdd(&qcnt, 1);
                shm.m.queue[q] = (u16)((row << 6) | j);
            }
        }
    }
    __syncthreads();

    const int n = qcnt;
    const float thr = thrp[0];
    for (int q = t; q < n; q += 256) {
        u16 v = shm.m.queue[q];
        int ti = v >> 6, j = v & 63;

        float A[16], B[16];
        const float4* Ap = (const float4*)&shm.m.sA[ti * 16];
        const float4* Bp = (const float4*)&shm.m.sB[j * 16];
#pragma unroll
        for (int r = 0; r < 4; r++) {
            float4 va = Ap[r], vb = Bp[r];
            A[r*4+0]=va.x; A[r*4+1]=va.y; A[r*4+2]=va.z; A[r*4+3]=va.w;
            B[r*4+0]=vb.x; B[r*4+1]=vb.y; B[r*4+2]=vb.z; B[r*4+3]=vb.w;
        }
        float inter = pair_inter_area(A, B);
        float iou = xdiv(inter, xadd(xsub(xadd(A[14], B[14]), inter), 1e-9f));
        if (iou > thr) atomicOr(&sbits[ti], 1ULL << j);
    }
    __syncthreads();

    if (t < 64) {
        u64 w = sbits[t];
        g_mask[(by * 64 + t) * NWORDS + bx] = w;   // block exclusively owns these words
        if (bx == by) g_diag[by * 64 + t] = w;
        if (w) atomicOr(&g_rownz[by], 1ULL << t);
    }

    // ---- completion: last of the 528 blocks runs the scan ----
    __threadfence();
    if (t == 0) {
        int d = atomicAdd(&g_done, 1);
        is_last = (d == NTILES - 1);
    }
    __syncthreads();
    if (!is_last) return;
    __threadfence();
    __syncthreads();   // smem union reuse barrier

    // ---- scan tail (one block, 256 threads) ----
    for (int i = t; i < NB; i += 256) shm.sdiag[i] = g_diag[i];   // coalesced 16KB
    if (t < NWORDS) snz[t] = g_rownz[t];
    __syncthreads();

    if (t == 0) {
        int acc = 0;
        for (int c = 0; c < NWORDS; c++) { cbase[c] = acc; acc += __popcll(snz[c]); }
        cbase[NWORDS] = acc;
    }
    __syncthreads();
    const int R = cbase[NWORDS];

    // slot -> global row map (parallel over chunks)
    if (t < NWORDS) {
        int slot = cbase[t];
        u64 m = snz[t];
        while (m) {
            int j = __ffsll((long long)m) - 1; m &= m - 1;
            if (slot < CAP_ROWS) rowid[slot] = t * 64 + j;
            slot++;
        }
    }
    __syncthreads();

    // copy suppressor rows into smem cache (coalesced 256B per row)
    const int Rc = (R < CAP_ROWS) ? R : CAP_ROWS;
    for (int w = t; w < Rc * NWORDS; w += 256)
        rowsbuf[w] = g_mask[(u32)rowid[w >> 5] * NWORDS + (w & 31)];
    __syncthreads();

    if (t < 32) {
        const int lane = t;
        u64 rem = 0ULL;   // lane's suppression word
        for (int c = 0; c < NWORDS; c++) {
            u64 cur = __shfl_sync(0xFFFFFFFFu, rem, c);

            u64 w0 = shm.sdiag[c * 64 + lane * 2];
            u64 w1 = shm.sdiag[c * 64 + lane * 2 + 1];
            u32 b0 = __ballot_sync(0xFFFFFFFFu, w0 != 0ULL);
            u32 b1 = __ballot_sync(0xFFFFFFFFu, w1 != 0ULL);
            u64 nzd = morton_even(b0) | (morton_even(b1) << 1);

            // sparse serial resolve (all lanes redundantly; smem broadcast)
            u64 A = 0ULL, covered = 0ULL;
            u64 m = nzd & ~cur;        // suppressed rows can't suppress others
            while (m) {
                int pbit = __ffsll((long long)m) - 1; m &= m - 1;
                u64 range = ((2ULL << pbit) - 1ULL) & ~covered;
                A |= (~cur) & range;
                covered |= range;
                if ((A >> pbit) & 1ULL) { cur |= shm.sdiag[c * 64 + pbit]; m &= ~cur; }
            }
            A |= (~cur) & ~covered;

            // OR full rows of alive suppressors from the smem cache
            u64 need = A & snz[c];
            const u64 sc = snz[c];
            const int base = cbase[c];
            while (need) {
                int j = __ffsll((long long)need) - 1; need &= need - 1;
                int slot = base + (int)__popcll(sc & ((1ULL << j) - 1ULL));
                u64 v = (slot < CAP_ROWS) ? rowsbuf[slot * NWORDS + lane]
                                          : g_mask[(u32)(c * 64 + j) * NWORDS + lane];
                rem |= v;
            }
            if (lane == 0) s_keep[c] = A;
        }
    }
    __syncthreads();

    for (int i = t; i < NB; i += 256) {
        int keep = (int)((s_keep[i >> 6] >> (i & 63)) & 1ULL);
        int orig = g_order[i];
        out[orig] = keep ? scores[orig] : 0.0f;
    }
}

// ---------------- launch ----------------
extern "C" void kernel_launch(void* const* d_in, const int* in_sizes, int n_in,
                              void* d_out, int out_size) {
    (void)in_sizes; (void)n_in; (void)out_size;
    const float* boxes  = (const float*)d_in[0];
    const float* scores = (const float*)d_in[1];
    const int*   labels = (const int*)d_in[2];
    const float* thr    = (const float*)d_in[3];
    float* out = (float*)d_out;

    cudaFuncSetAttribute(mask_scan_kernel, cudaFuncAttributeMaxDynamicSharedMemorySize,
                         SCAN_DYN_BYTES);

    prep_kernel<<<NB / 8, 256>>>(boxes, scores, labels);
    mask_scan_kernel<<<NTILES, 256, SCAN_DYN_BYTES>>>(thr, scores, out);
}

// round 13
// speedup vs baseline: 1.1913x; 1.1913x over previous
#include <cuda_runtime.h>
#include <cstdint>

#define NB 2048
#define NWORDS (NB / 64)                     // 32
#define NTILES (NWORDS * (NWORDS + 1) / 2)   // 528 upper-tri blocks
#define CAP_ROWS 640                         // suppressor-row smem cache capacity
#define SCAN_DYN_BYTES (CAP_ROWS * NWORDS * 8)   // 160KB

typedef unsigned long long u64;
typedef unsigned int u32;
typedef unsigned short u16;

// ---------------- device scratch ----------------
__device__ int   g_order[NB];              // sorted pos -> original index
__device__ __align__(16) float g_pboxs[NB * 16];  // SORTED: x0..3,y0..3,cx,cy,c,s,we,he,area,rad
__device__ u64   g_mask[NB * NWORDS];      // suppression bitmask; lower-tri never written, stays 0
__device__ u64   g_diag[NB];               // each row's diagonal-block word (contiguous copy)
__device__ u64   g_rownz[NWORDS];          // bit j of word c -> row c*64+j has any suppression

// exact (non-contracted) fp32 helpers — replicate jax/XLA unfused fp32 ops
__device__ __forceinline__ float xmul(float a, float b) { return __fmul_rn(a, b); }
__device__ __forceinline__ float xadd(float a, float b) { return __fadd_rn(a, b); }
__device__ __forceinline__ float xsub(float a, float b) { return __fsub_rn(a, b); }
__device__ __forceinline__ float xdiv(float a, float b) { return __fdiv_rn(a, b); }
__device__ __forceinline__ float xcross(float ax, float ay, float bx, float by) {
    return xsub(xmul(ax, by), xmul(ay, bx));
}

// ---------------- kernel 1: fused reduce + keys + rank + trig + precompute ----------------
// 256 blocks x 256 threads; 8 boxes per block (R9 mapping — best measured).
// Rank: warp-per-box, conflict-free interleaved smem scan.
// Trig: threads 0-15, ONE transcendental each (even=cos, odd=sin) -> half-length fp64 tail.
__global__ void __launch_bounds__(256) prep_kernel(const float* __restrict__ boxes,
                                                   const float* __restrict__ scores,
                                                   const int*   __restrict__ labels) {
    __shared__ u32  skeys[NB];
    __shared__ float red[256];
    __shared__ int  sranks[8];
    __shared__ float scos[8], ssin[8];
    const int tid  = threadIdx.x;
    const int warp = tid >> 5;
    const int lane = tid & 31;

    // redundant per-block reductions (max order-invariant; sqrt monotone -> exact)
    float m1 = -1e30f, m2 = -1e30f;
    for (int q = tid; q < NB; q += 256) {
        float cx = boxes[q * 5 + 0], cy = boxes[q * 5 + 1];
        float w  = boxes[q * 5 + 2], h  = boxes[q * 5 + 3];
        float s2 = xadd(xmul(w, w), xmul(h, h));
        m1 = fmaxf(m1, s2);
        m2 = fmaxf(m2, fmaxf(cx, cy));
        skeys[q] = __float_as_uint(scores[q]) ^ 0xFFFFFFFFu;   // ascending == descending score
    }
    red[tid] = m1; __syncthreads();
    for (int s = 128; s > 0; s >>= 1) { if (tid < s) red[tid] = fmaxf(red[tid], red[tid + s]); __syncthreads(); }
    float maxs = __fsqrt_rn(red[0]); __syncthreads();
    red[tid] = m2; __syncthreads();
    for (int s = 128; s > 0; s >>= 1) { if (tid < s) red[tid] = fmaxf(red[tid], red[tid + s]); __syncthreads(); }
    float maxc = red[0];

    // scale = (max_coord + max_radius)*2 + 1  (exact ref fp32 sequence)
    const float scale = xadd(xmul(xadd(maxc, xmul(maxs, 0.5f)), 2.0f), 1.0f);

    if (blockIdx.x == 0 && tid < NWORDS) g_rownz[tid] = 0ULL;

    // ---- trig: threads 0-15, one transcendental each (parallel half-length fp64 chains)
    if (tid < 16) {
        const int bi = tid >> 1;                       // local box 0..7
        const int i  = blockIdx.x * 8 + bi;
        double a = (double)boxes[i * 5 + 4];
        if (tid & 1) ssin[bi] = (float)sin(a);
        else         scos[bi] = (float)cos(a);
    }

    // ---- rank: warp `warp` ranks box i (interleaved -> bank == lane, conflict-free)
    {
        const int i = blockIdx.x * 8 + warp;
        const u32 mykey = skeys[i];
        int rank = 0;
#pragma unroll 16
        for (int q = lane; q < NB; q += 32) {
            u32 kq = skeys[q];
            rank += (kq < mykey) || (kq == mykey && q < i);   // stable tiebreak
        }
#pragma unroll
        for (int off = 16; off > 0; off >>= 1) rank += __shfl_xor_sync(0xFFFFFFFFu, rank, off);
        if (lane == 0) sranks[warp] = rank;
    }
    __syncthreads();

    // ---- precompute: threads 0-7, one box each (fp32 only — no long chains)
    if (tid < 8) {
        const int i = blockIdx.x * 8 + tid;
        const int rank = sranks[tid];

        float off = xmul((float)labels[i], scale);
        float cx = xadd(boxes[i * 5 + 0], off);
        float cy = xadd(boxes[i * 5 + 1], off);
        float w  = boxes[i * 5 + 2];
        float h  = boxes[i * 5 + 3];
        float c  = scos[tid];
        float s  = ssin[tid];
        float wh = xmul(w, 0.5f);
        float hh = xmul(h, 0.5f);

        float P[16];
#pragma unroll
        for (int q = 0; q < 4; q++) {
            float dx = (q == 1 || q == 2) ? wh : -wh;
            float dy = (q >= 2) ? hh : -hh;
            P[q]     = xsub(xadd(cx, xmul(c, dx)), xmul(s, dy));
            P[4 + q] = xadd(xadd(cy, xmul(s, dx)), xmul(c, dy));
        }
        P[8]  = cx;  P[9]  = cy;  P[10] = c;  P[11] = s;
        P[12] = xadd(wh, 1e-5f);
        P[13] = xadd(hh, 1e-5f);
        P[14] = xmul(w, h);
        P[15] = 0.5f * __fsqrt_rn(w * w + h * h) + 1e-2f;   // conservative circle radius

        float4* D = (float4*)&g_pboxs[rank * 16];
        const float4* Ps = (const float4*)P;
#pragma unroll
        for (int q = 0; q < 4; q++) D[q] = Ps[q];
        g_order[rank] = i;
    }
}

// ---------------- exact-replica pairwise intersection area (compacted) ----------------
__device__ __forceinline__ bool pib(float x, float y, const float* __restrict__ B) {
    float px = xsub(x, B[8]);
    float py = xsub(y, B[9]);
    float lx = xadd(xmul(B[10], px), xmul(B[11], py));     //  c*px + s*py
    float ly = xadd(xmul(-B[11], px), xmul(B[10], py));    // -s*px + c*py
    return (fabsf(lx) <= B[12]) && (fabsf(ly) <= B[13]);
}

__device__ float pair_inter_area(const float* __restrict__ A, const float* __restrict__ B) {
    float px[24], py[24];
    int k = 0;
    float sxm = 0.0f, sym = 0.0f;

    // candidate points appended in reference index order 0..23 -> identical fp sum order
#pragma unroll
    for (int q = 0; q < 4; q++) {
        if (pib(A[q], A[4 + q], B)) {
            px[k] = A[q]; py[k] = A[4 + q];
            sxm = xadd(sxm, A[q]); sym = xadd(sym, A[4 + q]); k++;
        }
    }
#pragma unroll
    for (int q = 0; q < 4; q++) {
        if (pib(B[q], B[4 + q], A)) {
            px[k] = B[q]; py[k] = B[4 + q];
            sxm = xadd(sxm, B[q]); sym = xadd(sym, B[4 + q]); k++;
        }
    }
#pragma unroll
    for (int ea = 0; ea < 4; ea++) {
        float pxx = A[ea], pyy = A[4 + ea];
        float rx = xsub(A[(ea + 1) & 3], pxx), ry = xsub(A[4 + ((ea + 1) & 3)], pyy);
#pragma unroll
        for (int eb = 0; eb < 4; eb++) {
            float qx = B[eb], qy = B[4 + eb];
            float sx = xsub(B[(eb + 1) & 3], qx), sy = xsub(B[4 + ((eb + 1) & 3)], qy);
            float den = xcross(rx, ry, sx, sy);
            float qpx = xsub(qx, pxx), qpy = xsub(qy, pyy);
            if (fabsf(den) > 1e-9f) {
                float tt = xdiv(xcross(qpx, qpy, sx, sy), den);
                float uu = xdiv(xcross(qpx, qpy, rx, ry), den);
                if (tt >= 0.0f && tt <= 1.0f && uu >= 0.0f && uu <= 1.0f) {
                    float ix = xadd(pxx, xmul(tt, rx));
                    float iy = xadd(pyy, xmul(tt, ry));
                    px[k] = ix; py[k] = iy;
                    sxm = xadd(sxm, ix); sym = xadd(sym, iy); k++;
                }
            }
        }
    }
    if (k < 3) return 0.0f;

    float kk  = (float)k;
    float cxm = xdiv(sxm, kk), cym = xdiv(sym, kk);

    float dxr[24], dyr[24];
    u64 key[24];
    for (int q = 0; q < k; q++) {
        float dx = xsub(px[q], cxm);
        float dy = xsub(py[q], cym);
        dxr[q] = dx; dyr[q] = dy;
        float a = atan2f(dy, dx);
        u32 b = __float_as_uint(a);
        b = (b & 0x80000000u) ? ~b : (b | 0x80000000u);   // monotone map
        key[q] = ((u64)b << 5) | (u32)q;                   // unique -> stable order
    }
    for (int q = 1; q < k; q++) {          // insertion sort, k typically 4-8
        u64 kq = key[q]; int r = q - 1;
        while (r >= 0 && key[r] > kq) { key[r + 1] = key[r]; r--; }
        key[r + 1] = kq;
    }

    float tot = 0.0f;
    for (int q = 0; q < k; q++) {
        int nq = (q + 1 < k) ? q + 1 : 0;
        int a0 = (int)(key[q]  & 31u);
        int a1 = (int)(key[nq] & 31u);
        tot = xadd(tot, xcross(dxr[a0], dyr[a0], dxr[a1], dyr[a1]));
    }
    return xmul(0.5f, fabsf(tot));
}

// ---------------- kernel 2: fused circle-filter + IoU per 64x64 tile ----------------
__global__ void __launch_bounds__(256) mask_kernel(const float* __restrict__ thrp) {
    // linear blockIdx -> upper-tri (by, bx)
    int b = blockIdx.x;
    int by = 0;
    while (b >= NWORDS - by) { b -= NWORDS - by; by++; }
    const int bx = by + b;
    const int t = threadIdx.x;

    __shared__ __align__(16) float sA[1024];
    __shared__ __align__(16) float sB[1024];
    __shared__ u64 sbits[64];
    __shared__ u16 queue[4096];
    __shared__ int qcnt;

    {   // float4 tile loads
        const float4* srcB = (const float4*)&g_pboxs[bx * 1024];
        const float4* srcA = (const float4*)&g_pboxs[by * 1024];
        float4* dB = (float4*)sB;
        float4* dA = (float4*)sA;
        if (t < 256) { dB[t] = srcB[t]; dA[t] = srcA[t]; }
    }
    if (t < 64) sbits[t] = 0ULL;
    if (t == 0) qcnt = 0;
    __syncthreads();

    // circle filter: 4 threads per row, 16 columns each
    {
        const int row = t & 63;
        const int qtr = t >> 6;
        const float acx = sA[row * 16 + 8];
        const float acy = sA[row * 16 + 9];
        const float ard = sA[row * 16 + 15];
        const int jlo = (bx == by) ? row + 1 : 0;
        const int j0 = qtr * 16, j1 = j0 + 16;
        for (int j = j0; j < j1; j++) {
            if (j < jlo) continue;
            float dx = acx - sB[j * 16 + 8], dy = acy - sB[j * 16 + 9];
            float rr = ard + sB[j * 16 + 15];
            if (dx * dx + dy * dy <= rr * rr) {          // circle overlap -> candidate
                int q = atomicAdd(&qcnt, 1);
                queue[q] = (u16)((row << 6) | j);
            }
        }
    }
    __syncthreads();

    const int n = qcnt;
    const float thr = thrp[0];
    for (int q = t; q < n; q += 256) {
        u16 v = queue[q];
        int ti = v >> 6, j = v & 63;

        float A[16], B[16];
        const float4* Ap = (const float4*)&sA[ti * 16];
        const float4* Bp = (const float4*)&sB[j * 16];
#pragma unroll
        for (int r = 0; r < 4; r++) {
            float4 va = Ap[r], vb = Bp[r];
            A[r*4+0]=va.x; A[r*4+1]=va.y; A[r*4+2]=va.z; A[r*4+3]=va.w;
            B[r*4+0]=vb.x; B[r*4+1]=vb.y; B[r*4+2]=vb.z; B[r*4+3]=vb.w;
        }
        float inter = pair_inter_area(A, B);
        float iou = xdiv(inter, xadd(xsub(xadd(A[14], B[14]), inter), 1e-9f));
        if (iou > thr) atomicOr(&sbits[ti], 1ULL << j);
    }
    __syncthreads();

    if (t < 64) {
        u64 w = sbits[t];
        g_mask[(by * 64 + t) * NWORDS + bx] = w;   // block exclusively owns these words
        if (bx == by) g_diag[by * 64 + t] = w;
        if (w) atomicOr(&g_rownz[by], 1ULL << t);
    }
}

// ---------------- kernel 3: greedy scan with smem row-cache ----------------
__device__ __forceinline__ u64 morton_even(u32 x) {
    u64 v = x;
    v = (v | (v << 16)) & 0x0000FFFF0000FFFFULL;
    v = (v | (v << 8))  & 0x00FF00FF00FF00FFULL;
    v = (v | (v << 4))  & 0x0F0F0F0F0F0F0F0FULL;
    v = (v | (v << 2))  & 0x3333333333333333ULL;
    v = (v | (v << 1))  & 0x5555555555555555ULL;
    return v;
}

__global__ void __launch_bounds__(256) scan_kernel(const float* __restrict__ scores,
                                                   float* __restrict__ out) {
    extern __shared__ u64 rowsbuf[];     // CAP_ROWS x NWORDS words (dynamic, 160KB)
    __shared__ u64 sdiag[NB];            // 16KB
    __shared__ u64 snz[NWORDS], s_keep[NWORDS];
    __shared__ int cbase[NWORDS + 1];
    __shared__ int rowid[CAP_ROWS];
    const int t = threadIdx.x;

    for (int i = t; i < NB; i += 256) sdiag[i] = g_diag[i];   // coalesced 16KB
    if (t < NWORDS) snz[t] = g_rownz[t];
    __syncthreads();

    if (t == 0) {
        int acc = 0;
        for (int c = 0; c < NWORDS; c++) { cbase[c] = acc; acc += __popcll(snz[c]); }
        cbase[NWORDS] = acc;
    }
    __syncthreads();
    const int R = cbase[NWORDS];

    // slot -> global row map (parallel over chunks)
    if (t < NWORDS) {
        int slot = cbase[t];
        u64 m = snz[t];
        while (m) {
            int j = __ffsll((long long)m) - 1; m &= m - 1;
            if (slot < CAP_ROWS) rowid[slot] = t * 64 + j;
            slot++;
        }
    }
    __syncthreads();

    // copy suppressor rows into smem cache (coalesced 256B per row)
    const int Rc = (R < CAP_ROWS) ? R : CAP_ROWS;
    for (int w = t; w < Rc * NWORDS; w += 256)
        rowsbuf[w] = g_mask[(u32)rowid[w >> 5] * NWORDS + (w & 31)];
    __syncthreads();

    if (t < 32) {
        const int lane = t;
        u64 rem = 0ULL;   // lane's suppression word
        for (int c = 0; c < NWORDS; c++) {
            u64 cur = __shfl_sync(0xFFFFFFFFu, rem, c);

            u64 w0 = sdiag[c * 64 + lane * 2];
            u64 w1 = sdiag[c * 64 + lane * 2 + 1];
            u32 b0 = __ballot_sync(0xFFFFFFFFu, w0 != 0ULL);
            u32 b1 = __ballot_sync(0xFFFFFFFFu, w1 != 0ULL);
            u64 nzd = morton_even(b0) | (morton_even(b1) << 1);

            // sparse serial resolve (all lanes redundantly; smem broadcast)
            u64 A = 0ULL, covered = 0ULL;
            u64 m = nzd & ~cur;        // suppressed rows can't suppress others
            while (m) {
                int pbit = __ffsll((long long)m) - 1; m &= m - 1;
                u64 range = ((2ULL << pbit) - 1ULL) & ~covered;
                A |= (~cur) & range;
                covered |= range;
                if ((A >> pbit) & 1ULL) { cur |= sdiag[c * 64 + pbit]; m &= ~cur; }
            }
            A |= (~cur) & ~covered;

            // OR full rows of alive suppressors from the smem cache
            u64 need = A & snz[c];
            const u64 sc = snz[c];
            const int base = cbase[c];
            while (need) {
                int j = __ffsll((long long)need) - 1; need &= need - 1;
                int slot = base + (int)__popcll(sc & ((1ULL << j) - 1ULL));
                u64 v = (slot < CAP_ROWS) ? rowsbuf[slot * NWORDS + lane]
                                          : g_mask[(u32)(c * 64 + j) * NWORDS + lane];
                rem |= v;
            }
            if (lane == 0) s_keep[c] = A;
        }
    }
    __syncthreads();

    for (int i = t; i < NB; i += 256) {
        int keep = (int)((s_keep[i >> 6] >> (i & 63)) & 1ULL);
        int orig = g_order[i];
        out[orig] = keep ? scores[orig] : 0.0f;
    }
}

// ---------------- launch ----------------
extern "C" void kernel_launch(void* const* d_in, const int* in_sizes, int n_in,
                              void* d_out, int out_size) {
    (void)in_sizes; (void)n_in; (void)out_size;
    const float* boxes  = (const float*)d_in[0];
    const float* scores = (const float*)d_in[1];
    const int*   labels = (const int*)d_in[2];
    const float* thr    = (const float*)d_in[3];
    float* out = (float*)d_out;

    cudaFuncSetAttribute(scan_kernel, cudaFuncAttributeMaxDynamicSharedMemorySize,
                         SCAN_DYN_BYTES);

    prep_kernel<<<NB / 8, 256>>>(boxes, scores, labels);
    mask_kernel<<<NTILES, 256>>>(thr);
    scan_kernel<<<1, 256, SCAN_DYN_BYTES>>>(scores, out);
}

// round 14
// speedup vs baseline: 1.2604x; 1.0580x over previous
#include <cuda_runtime.h>
#include <cstdint>

#define NB 2048
#define NWORDS (NB / 64)                     // 32
#define NTILES (NWORDS * (NWORDS + 1) / 2)   // 528 upper-tri blocks
#define CAP_ROWS 640                         // suppressor-row smem cache capacity
#define SCAN_DYN_BYTES (CAP_ROWS * NWORDS * 8)   // 160KB

typedef unsigned long long u64;
typedef unsigned int u32;
typedef unsigned short u16;

// ---------------- device scratch ----------------
__device__ int   g_order[NB];              // sorted pos -> original index
__device__ __align__(16) float g_pboxs[NB * 16];  // SORTED: x0..3,y0..3,cx,cy,c,s,we,he,area,rad
__device__ u64   g_mask[NB * NWORDS];      // suppression bitmask; lower-tri never written, stays 0
__device__ u64   g_diag[NB];               // each row's diagonal-block word (contiguous copy)
__device__ u64   g_rownz[NWORDS];          // bit j of word c -> row c*64+j has any suppression

// exact (non-contracted) fp32 helpers — replicate jax/XLA unfused fp32 ops
__device__ __forceinline__ float xmul(float a, float b) { return __fmul_rn(a, b); }
__device__ __forceinline__ float xadd(float a, float b) { return __fadd_rn(a, b); }
__device__ __forceinline__ float xsub(float a, float b) { return __fsub_rn(a, b); }
__device__ __forceinline__ float xdiv(float a, float b) { return __fdiv_rn(a, b); }
__device__ __forceinline__ float xcross(float ax, float ay, float bx, float by) {
    return xsub(xmul(ax, by), xmul(ay, bx));
}

// ---------------- kernel 1: warp-specialized prep ----------------
// 256 blocks x 384 threads; 8 boxes per block.
// Warps 0-7: rank (conflict-free interleaved smem scan).
// Warp 8 lanes 0-15: trig (one transcendental per lane).
// Warps 9-11: box max-reduction (order-invariant; shfl partials).
// All three phases run CONCURRENTLY on different warps.
__global__ void __launch_bounds__(384) prep_kernel(const float* __restrict__ boxes,
                                                   const float* __restrict__ scores,
                                                   const int*   __restrict__ labels) {
    __shared__ __align__(16) u32 skeys[NB];
    __shared__ int   sranks[8];
    __shared__ float scos[8], ssin[8];
    __shared__ float r_s2[3], r_c[3];
    const int tid  = threadIdx.x;
    const int warp = tid >> 5;
    const int lane = tid & 31;

    // vectorized key load: 512 uint4 across 384 threads
    {
        const uint4* sc4 = (const uint4*)scores;
        uint4* sk4 = (uint4*)skeys;
        for (int q = tid; q < NB / 4; q += 384) {
            uint4 v = sc4[q];
            v.x ^= 0xFFFFFFFFu; v.y ^= 0xFFFFFFFFu;
            v.z ^= 0xFFFFFFFFu; v.w ^= 0xFFFFFFFFu;
            sk4[q] = v;          // ascending == descending score
        }
    }
    if (blockIdx.x == 0 && tid >= 256 && tid - 256 < NWORDS) g_rownz[tid - 256] = 0ULL;
    __syncthreads();

    if (warp < 8) {
        // ---- rank: warp `warp` ranks box i (interleaved -> bank == lane, conflict-free)
        const int i = blockIdx.x * 8 + warp;
        const u32 mykey = skeys[i];
        int rank = 0;
#pragma unroll 16
        for (int q = lane; q < NB; q += 32) {
            u32 kq = skeys[q];
            rank += (kq < mykey) || (kq == mykey && q < i);   // stable tiebreak
        }
#pragma unroll
        for (int off = 16; off > 0; off >>= 1) rank += __shfl_xor_sync(0xFFFFFFFFu, rank, off);
        if (lane == 0) sranks[warp] = rank;
    } else if (warp == 8) {
        // ---- trig: lanes 0-15, one transcendental each
        if (lane < 16) {
            const int bi = lane >> 1;                  // local box 0..7
            const int i  = blockIdx.x * 8 + bi;
            double a = (double)boxes[i * 5 + 4];
            if (lane & 1) ssin[bi] = (float)sin(a);
            else          scos[bi] = (float)cos(a);
        }
    } else {
        // ---- box max-reduction: warps 9-11 (96 threads); max order-invariant -> exact
        const int t96 = tid - 288;
        float m1 = -1e30f, m2 = -1e30f;
        for (int q = t96; q < NB; q += 96) {
            float cx = boxes[q * 5 + 0], cy = boxes[q * 5 + 1];
            float w  = boxes[q * 5 + 2], h  = boxes[q * 5 + 3];
            float s2 = xadd(xmul(w, w), xmul(h, h));
            m1 = fmaxf(m1, s2);
            m2 = fmaxf(m2, fmaxf(cx, cy));
        }
#pragma unroll
        for (int off = 16; off > 0; off >>= 1) {
            m1 = fmaxf(m1, __shfl_xor_sync(0xFFFFFFFFu, m1, off));
            m2 = fmaxf(m2, __shfl_xor_sync(0xFFFFFFFFu, m2, off));
        }
        if (lane == 0) { r_s2[warp - 9] = m1; r_c[warp - 9] = m2; }
    }
    __syncthreads();

    // ---- precompute: threads 0-7, one box each (fp32 only)
    if (tid < 8) {
        float v  = fmaxf(fmaxf(r_s2[0], r_s2[1]), r_s2[2]);
        float c0 = fmaxf(fmaxf(r_c[0],  r_c[1]),  r_c[2]);
        float maxs = __fsqrt_rn(v);    // sqrt monotone & correctly rounded
        // scale = (max_coord + max_radius)*2 + 1  (exact ref fp32 sequence)
        const float scale = xadd(xmul(xadd(c0, xmul(maxs, 0.5f)), 2.0f), 1.0f);

        const int i = blockIdx.x * 8 + tid;
        const int rank = sranks[tid];

        float off = xmul((float)labels[i], scale);
        float cx = xadd(boxes[i * 5 + 0], off);
        float cy = xadd(boxes[i * 5 + 1], off);
        float w  = boxes[i * 5 + 2];
        float h  = boxes[i * 5 + 3];
        float c  = scos[tid];
        float s  = ssin[tid];
        float wh = xmul(w, 0.5f);
        float hh = xmul(h, 0.5f);

        float P[16];
#pragma unroll
        for (int q = 0; q < 4; q++) {
            float dx = (q == 1 || q == 2) ? wh : -wh;
            float dy = (q >= 2) ? hh : -hh;
            P[q]     = xsub(xadd(cx, xmul(c, dx)), xmul(s, dy));
            P[4 + q] = xadd(xadd(cy, xmul(s, dx)), xmul(c, dy));
        }
        P[8]  = cx;  P[9]  = cy;  P[10] = c;  P[11] = s;
        P[12] = xadd(wh, 1e-5f);
        P[13] = xadd(hh, 1e-5f);
        P[14] = xmul(w, h);
        P[15] = 0.5f * __fsqrt_rn(w * w + h * h) + 1e-2f;   // conservative circle radius

        float4* D = (float4*)&g_pboxs[rank * 16];
        const float4* Ps = (const float4*)P;
#pragma unroll
        for (int q = 0; q < 4; q++) D[q] = Ps[q];
        g_order[rank] = i;
    }
}

// ---------------- exact-replica pairwise intersection area (compacted) ----------------
__device__ __forceinline__ bool pib(float x, float y, const float* __restrict__ B) {
    float px = xsub(x, B[8]);
    float py = xsub(y, B[9]);
    float lx = xadd(xmul(B[10], px), xmul(B[11], py));     //  c*px + s*py
    float ly = xadd(xmul(-B[11], px), xmul(B[10], py));    // -s*px + c*py
    return (fabsf(lx) <= B[12]) && (fabsf(ly) <= B[13]);
}

__device__ float pair_inter_area(const float* __restrict__ A, const float* __restrict__ B) {
    float px[24], py[24];
    int k = 0;
    float sxm = 0.0f, sym = 0.0f;

    // candidate points appended in reference index order 0..23 -> identical fp sum order
#pragma unroll
    for (int q = 0; q < 4; q++) {
        if (pib(A[q], A[4 + q], B)) {
            px[k] = A[q]; py[k] = A[4 + q];
            sxm = xadd(sxm, A[q]); sym = xadd(sym, A[4 + q]); k++;
        }
    }
#pragma unroll
    for (int q = 0; q < 4; q++) {
        if (pib(B[q], B[4 + q], A)) {
            px[k] = B[q]; py[k] = B[4 + q];
            sxm = xadd(sxm, B[q]); sym = xadd(sym, B[4 + q]); k++;
        }
    }
#pragma unroll
    for (int ea = 0; ea < 4; ea++) {
        float pxx = A[ea], pyy = A[4 + ea];
        float rx = xsub(A[(ea + 1) & 3], pxx), ry = xsub(A[4 + ((ea + 1) & 3)], pyy);
#pragma unroll
        for (int eb = 0; eb < 4; eb++) {
            float qx = B[eb], qy = B[4 + eb];
            float sx = xsub(B[(eb + 1) & 3], qx), sy = xsub(B[4 + ((eb + 1) & 3)], qy);
            float den = xcross(rx, ry, sx, sy);
            float qpx = xsub(qx, pxx), qpy = xsub(qy, pyy);
            if (fabsf(den) > 1e-9f) {
                float tt = xdiv(xcross(qpx, qpy, sx, sy), den);
                float uu = xdiv(xcross(qpx, qpy, rx, ry), den);
                if (tt >= 0.0f && tt <= 1.0f && uu >= 0.0f && uu <= 1.0f) {
                    float ix = xadd(pxx, xmul(tt, rx));
                    float iy = xadd(pyy, xmul(tt, ry));
                    px[k] = ix; py[k] = iy;
                    sxm = xadd(sxm, ix); sym = xadd(sym, iy); k++;
                }
            }
        }
    }
    if (k < 3) return 0.0f;

    float kk  = (float)k;
    float cxm = xdiv(sxm, kk), cym = xdiv(sym, kk);

    float dxr[24], dyr[24];
    u64 key[24];
    for (int q = 0; q < k; q++) {
        float dx = xsub(px[q], cxm);
        float dy = xsub(py[q], cym);
        dxr[q] = dx; dyr[q] = dy;
        float a = atan2f(dy, dx);
        u32 b = __float_as_uint(a);
        b = (b & 0x80000000u) ? ~b : (b | 0x80000000u);   // monotone map
        key[q] = ((u64)b << 5) | (u32)q;                   // unique -> stable order
    }
    for (int q = 1; q < k; q++) {          // insertion sort, k typically 4-8
        u64 kq = key[q]; int r = q - 1;
        while (r >= 0 && key[r] > kq) { key[r + 1] = key[r]; r--; }
        key[r + 1] = kq;
    }

    float tot = 0.0f;
    for (int q = 0; q < k; q++) {
        int nq = (q + 1 < k) ? q + 1 : 0;
        int a0 = (int)(key[q]  & 31u);
        int a1 = (int)(key[nq] & 31u);
        tot = xadd(tot, xcross(dxr[a0], dyr[a0], dxr[a1], dyr[a1]));
    }
    return xmul(0.5f, fabsf(tot));
}

// ---------------- kernel 2: fused circle-filter + IoU per 64x64 tile ----------------
__global__ void __launch_bounds__(256) mask_kernel(const float* __restrict__ thrp) {
    // linear blockIdx -> upper-tri (by, bx)
    int b = blockIdx.x;
    int by = 0;
    while (b >= NWORDS - by) { b -= NWORDS - by; by++; }
    const int bx = by + b;
    const int t = threadIdx.x;

    __shared__ __align__(16) float sA[1024];
    __shared__ __align__(16) float sB[1024];
    __shared__ u64 sbits[64];
    __shared__ u16 queue[4096];
    __shared__ int qcnt;

    {   // float4 tile loads
        const float4* srcB = (const float4*)&g_pboxs[bx * 1024];
        const float4* srcA = (const float4*)&g_pboxs[by * 1024];
        float4* dB = (float4*)sB;
        float4* dA = (float4*)sA;
        if (t < 256) { dB[t] = srcB[t]; dA[t] = srcA[t]; }
    }
    if (t < 64) sbits[t] = 0ULL;
    if (t == 0) qcnt = 0;
    __syncthreads();

    // circle filter: 4 threads per row, 16 columns each
    {
        const int row = t & 63;
        const int qtr = t >> 6;
        const float acx = sA[row * 16 + 8];
        const float acy = sA[row * 16 + 9];
        const float ard = sA[row * 16 + 15];
        const int jlo = (bx == by) ? row + 1 : 0;
        const int j0 = qtr * 16, j1 = j0 + 16;
        for (int j = j0; j < j1; j++) {
            if (j < jlo) continue;
            float dx = acx - sB[j * 16 + 8], dy = acy - sB[j * 16 + 9];
            float rr = ard + sB[j * 16 + 15];
            if (dx * dx + dy * dy <= rr * rr) {          // circle overlap -> candidate
                int q = atomicAdd(&qcnt, 1);
                queue[q] = (u16)((row << 6) | j);
            }
        }
    }
    __syncthreads();

    const int n = qcnt;
    const float thr = thrp[0];
    for (int q = t; q < n; q += 256) {
        u16 v = queue[q];
        int ti = v >> 6, j = v & 63;

        float A[16], B[16];
        const float4* Ap = (const float4*)&sA[ti * 16];
        const float4* Bp = (const float4*)&sB[j * 16];
#pragma unroll
        for (int r = 0; r < 4; r++) {
            float4 va = Ap[r], vb = Bp[r];
            A[r*4+0]=va.x; A[r*4+1]=va.y; A[r*4+2]=va.z; A[r*4+3]=va.w;
            B[r*4+0]=vb.x; B[r*4+1]=vb.y; B[r*4+2]=vb.z; B[r*4+3]=vb.w;
        }
        float inter = pair_inter_area(A, B);
        float iou = xdiv(inter, xadd(xsub(xadd(A[14], B[14]), inter), 1e-9f));
        if (iou > thr) atomicOr(&sbits[ti], 1ULL << j);
    }
    __syncthreads();

    if (t < 64) {
        u64 w = sbits[t];
        g_mask[(by * 64 + t) * NWORDS + bx] = w;   // block exclusively owns these words
        if (bx == by) g_diag[by * 64 + t] = w;
        if (w) atomicOr(&g_rownz[by], 1ULL << t);
    }
}

// ---------------- kernel 3: greedy scan with smem row-cache ----------------
__device__ __forceinline__ u64 morton_even(u32 x) {
    u64 v = x;
    v = (v | (v << 16)) & 0x0000FFFF0000FFFFULL;
    v = (v | (v << 8))  & 0x00FF00FF00FF00FFULL;
    v = (v | (v << 4))  & 0x0F0F0F0F0F0F0F0FULL;
    v = (v | (v << 2))  & 0x3333333333333333ULL;
    v = (v | (v << 1))  & 0x5555555555555555ULL;
    return v;
}

__global__ void __launch_bounds__(256) scan_kernel(const float* __restrict__ scores,
                                                   float* __restrict__ out) {
    extern __shared__ u64 rowsbuf[];     // CAP_ROWS x NWORDS words (dynamic, 160KB)
    __shared__ u64 sdiag[NB];            // 16KB
    __shared__ u64 snz[NWORDS], s_keep[NWORDS];
    __shared__ int cbase[NWORDS + 1];
    __shared__ int rowid[CAP_ROWS];
    const int t = threadIdx.x;

    for (int i = t; i < NB; i += 256) sdiag[i] = g_diag[i];   // coalesced 16KB
    if (t < NWORDS) snz[t] = g_rownz[t];
    __syncthreads();

    if (t == 0) {
        int acc = 0;
        for (int c = 0; c < NWORDS; c++) { cbase[c] = acc; acc += __popcll(snz[c]); }
        cbase[NWORDS] = acc;
    }
    __syncthreads();
    const int R = cbase[NWORDS];

    // slot -> global row map (parallel over chunks)
    if (t < NWORDS) {
        int slot = cbase[t];
        u64 m = snz[t];
        while (m) {
            int j = __ffsll((long long)m) - 1; m &= m - 1;
            if (slot < CAP_ROWS) rowid[slot] = t * 64 + j;
            slot++;
        }
    }
    __syncthreads();

    // copy suppressor rows into smem cache (coalesced 256B per row)
    const int Rc = (R < CAP_ROWS) ? R : CAP_ROWS;
    for (int w = t; w < Rc * NWORDS; w += 256)
        rowsbuf[w] = g_mask[(u32)rowid[w >> 5] * NWORDS + (w & 31)];
    __syncthreads();

    if (t < 32) {
        const int lane = t;
        u64 rem = 0ULL;   // lane's suppression word
        for (int c = 0; c < NWORDS; c++) {
            u64 cur = __shfl_sync(0xFFFFFFFFu, rem, c);

            u64 w0 = sdiag[c * 64 + lane * 2];
            u64 w1 = sdiag[c * 64 + lane * 2 + 1];
            u32 b0 = __ballot_sync(0xFFFFFFFFu, w0 != 0ULL);
            u32 b1 = __ballot_sync(0xFFFFFFFFu, w1 != 0ULL);
            u64 nzd = morton_even(b0) | (morton_even(b1) << 1);

            // sparse serial resolve (all lanes redundantly; smem broadcast)
            u64 A = 0ULL, covered = 0ULL;
            u64 m = nzd & ~cur;        // suppressed rows can't suppress others
            while (m) {
                int pbit = __ffsll((long long)m) - 1; m &= m - 1;
                u64 range = ((2ULL << pbit) - 1ULL) & ~covered;
                A |= (~cur) & range;
                covered |= range;
                if ((A >> pbit) & 1ULL) { cur |= sdiag[c * 64 + pbit]; m &= ~cur; }
            }
            A |= (~cur) & ~covered;

            // OR full rows of alive suppressors from the smem cache
            u64 need = A & snz[c];
            const u64 sc = snz[c];
            const int base = cbase[c];
            while (need) {
                int j = __ffsll((long long)need) - 1; need &= need - 1;
                int slot = base + (int)__popcll(sc & ((1ULL << j) - 1ULL));
                u64 v = (slot < CAP_ROWS) ? rowsbuf[slot * NWORDS + lane]
                                          : g_mask[(u32)(c * 64 + j) * NWORDS + lane];
                rem |= v;
            }
            if (lane == 0) s_keep[c] = A;
        }
    }
    __syncthreads();

    for (int i = t; i < NB; i += 256) {
        int keep = (int)((s_keep[i >> 6] >> (i & 63)) & 1ULL);
        int orig = g_order[i];
        out[orig] = keep ? scores[orig] : 0.0f;
    }
}

// ---------------- launch ----------------
extern "C" void kernel_launch(void* const* d_in, const int* in_sizes, int n_in,
                              void* d_out, int out_size) {
    (void)in_sizes; (void)n_in; (void)out_size;
    const float* boxes  = (const float*)d_in[0];
    const float* scores = (const float*)d_in[1];
    const int*   labels = (const int*)d_in[2];
    const float* thr    = (const float*)d_in[3];
    float* out = (float*)d_out;

    cudaFuncSetAttribute(scan_kernel, cudaFuncAttributeMaxDynamicSharedMemorySize,
                         SCAN_DYN_BYTES);

    prep_kernel<<<NB / 8, 384>>>(boxes, scores, labels);
    mask_kernel<<<NTILES, 256>>>(thr);
    scan_kernel<<<1, 256, SCAN_DYN_BYTES>>>(scores, out);
}